// round 14
// baseline (speedup 1.0000x reference)
#include <cuda_runtime.h>
#include <cuda_fp16.h>
#include <cstdint>

#define SS 2048
#define DD 64
#define NBH 32
#define QT 32
#define KCH 64
#define NCH 32
#define C_EXP 0.18033688011112042f      // 0.125 * log2(e)

#define CTX_ELEMS (2LL*16*2048*64)
#define PROB_ELEMS (2LL*16*2048*2048)

__device__ __half g_kh[NBH*SS*DD];
__device__ __half g_vh[NBH*SS*DD];

__global__ void prep_split_kernel(const float* __restrict__ K,
                                  const float* __restrict__ V)
{
    int i = blockIdx.x * 256 + threadIdx.x;
    g_kh[i] = __float2half_rn(K[i]);
    g_vh[i] = __float2half_rn(V[i]);
}

// ---------------- smem: per-WARP self staging ---------------------------------
// warp w owns 2 stages of [K slice 2304B | V slice 2304B]
#define SLICE_B 2304                    // 16 rows x 144B
#define STAGE_B 4608
#define WARP_B  9216                    // 2 stages
#define OFF_RSUM 73728                  // 8 warps x 9216
#define OFF_RINV 73856
#define SMEM_BYTES 73984

__device__ __forceinline__ uint32_t sptr(const void* p) {
    return (uint32_t)__cvta_generic_to_shared(p);
}
__device__ __forceinline__ void ldmA(uint32_t* a, uint32_t addr) {
    asm volatile("ldmatrix.sync.aligned.m8n8.x4.shared.b16 {%0,%1,%2,%3}, [%4];"
                 : "=r"(a[0]), "=r"(a[1]), "=r"(a[2]), "=r"(a[3]) : "r"(addr));
}
__device__ __forceinline__ void ldmB4(uint32_t* b, uint32_t addr) {
    asm volatile("ldmatrix.sync.aligned.m8n8.x4.shared.b16 {%0,%1,%2,%3}, [%4];"
                 : "=r"(b[0]), "=r"(b[1]), "=r"(b[2]), "=r"(b[3]) : "r"(addr));
}
__device__ __forceinline__ void ldmBT4(uint32_t* b, uint32_t addr) {
    asm volatile("ldmatrix.sync.aligned.m8n8.x4.trans.shared.b16 {%0,%1,%2,%3}, [%4];"
                 : "=r"(b[0]), "=r"(b[1]), "=r"(b[2]), "=r"(b[3]) : "r"(addr));
}
__device__ __forceinline__ void mma16816(float* c, const uint32_t* a, const uint32_t* b) {
    asm volatile("mma.sync.aligned.m16n8k16.row.col.f32.f16.f16.f32 "
                 "{%0,%1,%2,%3}, {%4,%5,%6,%7}, {%8,%9}, {%0,%1,%2,%3};"
                 : "+f"(c[0]), "+f"(c[1]), "+f"(c[2]), "+f"(c[3])
                 : "r"(a[0]), "r"(a[1]), "r"(a[2]), "r"(a[3]), "r"(b[0]), "r"(b[1]));
}
__device__ __forceinline__ void cpa16(uint32_t dst, const void* src) {
    asm volatile("cp.async.cg.shared.global [%0], [%1], 16;" :: "r"(dst), "l"(src));
}
__device__ __forceinline__ void cpa_commit() {
    asm volatile("cp.async.commit_group;");
}
template<int N> __device__ __forceinline__ void cpa_wait() {
    asm volatile("cp.async.wait_group %0;" :: "n"(N));
}
__device__ __forceinline__ float ex2f(float x) {
    float y; asm("ex2.approx.f32 %0, %1;" : "=f"(y) : "f"(x)); return y;
}
__device__ __forceinline__ uint32_t packh2(float a, float b) {
    __half2 t = __floats2half2_rn(a, b);
    return *(uint32_t*)&t;
}

__global__ __launch_bounds__(256, 3)
void sdpa_kernel(const float* __restrict__ Qg_,
                 const int*   __restrict__ Mg_,
                 float* __restrict__ ctx_out,
                 float* __restrict__ prob_out)
{
    extern __shared__ char smem[];
    float* rsum_s = (float*)(smem + OFF_RSUM);
    float* rinv_s = (float*)(smem + OFF_RINV);

    const int tid = threadIdx.x;
    const int w = tid >> 5, l = tid & 31;
    const int bh = blockIdx.x >> 6;
    const int qt = blockIdx.x & 63;
    const int q0 = qt * QT;
    const int b  = bh >> 4;
    const int mh = w & 1;               // m-half: rows 16*mh..
    const int ns = w >> 1;              // key-slice 16*ns.. (0..3)
    const int lr = l >> 2;
    const int lc = (l & 3) * 2;
    const int r0 = 16 * mh + lr;

    const float* Qg = Qg_ + ((size_t)bh * SS + q0) * DD;
    const int*   mg = Mg_ + (size_t)b * SS;

    // ---- Q load via borrowed staging smem; rowsum init ----
    __half* qtmp = (__half*)smem;
    for (int i = tid; i < QT * DD; i += 256) {
        int r = i >> 6, d = i & 63;
        qtmp[r * 72 + d] = __float2half_rn(Qg[i]);
    }
    if (tid < 32) rsum_s[tid] = 0.f;
    __syncthreads();

    uint32_t qh[16];
    {
        uint32_t qb = sptr(qtmp) + (16 * mh + (l & 15)) * 144 + (l >> 4) * 16;
#pragma unroll
        for (int kt = 0; kt < 4; kt++) ldmA(qh + 4 * kt, qb + kt * 32);
    }
    __syncthreads();                    // Q consumed; staging free

    // ---- warp-self staging: this warp loads BOTH its K and V 16-key slices --
    const __half* gKs = g_kh + ((size_t)bh * SS + 16 * ns) * DD;   // slice base
    const __half* gVs = g_vh + ((size_t)bh * SS + 16 * ns) * DD;
    const uint32_t wbase = sptr(smem) + w * WARP_B;
    // coalesced: lane l -> dst row (l>>3)+4j, seg l&7 ; src contiguous 512B/sweep
    const uint32_t dOff = (l >> 3) * 144 + (l & 7) * 16;
    const int      sOff = l * 8;        // halfs

    auto issue = [&](int ch) {
        uint32_t dK = wbase + (ch & 1) * STAGE_B + dOff;
        const __half* sK = gKs + (size_t)ch * KCH * DD + sOff;
        const __half* sV = gVs + (size_t)ch * KCH * DD + sOff;
#pragma unroll
        for (int j = 0; j < 4; j++) {
            cpa16(dK + j * 576, sK + j * 256);
            cpa16(dK + SLICE_B + j * 576, sV + j * 256);
        }
        cpa_commit();
    };
    issue(0); issue(1);

    const uint32_t kOff4 = (8 * (l >> 4) + (l & 7)) * 144 + ((l >> 3) & 1) * 16;
    const uint32_t vOff4 = (l & 15) * 144 + (l >> 4) * 16 + SLICE_B;
    float* probRow = prob_out ? prob_out + ((size_t)bh * SS + q0 + r0) * SS : nullptr;

    float pv[8][4] = {};
    float rs0 = 0.f, rs1 = 0.f;

#pragma unroll 1
    for (int ch = 0; ch < NCH; ch++) {
        if (ch < NCH - 1) cpa_wait<1>();     // group ch complete (ch+1 may fly)
        else              cpa_wait<0>();
        __syncwarp();                        // cross-lane visibility (warp-local)

        const uint32_t base = wbase + (ch & 1) * STAGE_B;

        // ---- QK^T: rows 16mh..+15, keys 16ns..+15 ----
        float acc[2][4] = {};
        uint32_t bq[4];
#pragma unroll
        for (int kt = 0; kt < 4; kt++) {
            ldmB4(bq, base + kOff4 + kt * 32);
            mma16816(acc[0], qh + 4 * kt, bq);
            mma16816(acc[1], qh + 4 * kt, bq + 2);
        }

        // ---- exp + mask + pack ----
        const int kb = ch * KCH + 16 * ns + lc;
        float p[8];
        uint32_t pah[4];
#pragma unroll
        for (int t = 0; t < 2; t++) {
            int2 mm = *(const int2*)(mg + kb + 8 * t);
            p[4*t+0] = mm.x ? 0.f : ex2f(acc[t][0] * C_EXP);
            p[4*t+1] = mm.y ? 0.f : ex2f(acc[t][1] * C_EXP);
            p[4*t+2] = mm.x ? 0.f : ex2f(acc[t][2] * C_EXP);
            p[4*t+3] = mm.y ? 0.f : ex2f(acc[t][3] * C_EXP);
            rs0 += p[4*t+0] + p[4*t+1];
            rs1 += p[4*t+2] + p[4*t+3];
            pah[2*t]   = packh2(p[4*t+0], p[4*t+1]);
            pah[2*t+1] = packh2(p[4*t+2], p[4*t+3]);
        }

        // ---- PV (critical path) ----
        uint32_t bv[4];
#pragma unroll
        for (int jj = 0; jj < 4; jj++) {
            ldmBT4(bv, base + vOff4 + jj * 32);
            mma16816(pv[2 * jj],     pah, bv);
            mma16816(pv[2 * jj + 1], pah, bv + 2);
        }

        // ---- prefetch next+1 (stage reads done: QK+PV both finished) ----
        if (ch + 2 < NCH) issue(ch + 2);

        // ---- prob stores (unnormalized) ----
        if (probRow) {
#pragma unroll
            for (int t = 0; t < 2; t++) {
                *(float2*)(probRow + kb + 8 * t)          = make_float2(p[4*t+0], p[4*t+1]);
                *(float2*)(probRow + 8 * SS + kb + 8 * t) = make_float2(p[4*t+2], p[4*t+3]);
            }
        }
    }

    // ---- rowsum reduce ----
    rs0 += __shfl_xor_sync(0xffffffffu, rs0, 1);
    rs0 += __shfl_xor_sync(0xffffffffu, rs0, 2);
    rs1 += __shfl_xor_sync(0xffffffffu, rs1, 1);
    rs1 += __shfl_xor_sync(0xffffffffu, rs1, 2);
    if ((l & 3) == 0) {
        atomicAdd(&rsum_s[r0], rs0);
        atomicAdd(&rsum_s[r0 + 8], rs1);
    }
    __syncthreads();                    // all warps done with staging + atomics

    if (tid < 32) rinv_s[tid] = 1.0f / rsum_s[tid];

    // ---- cross-warp PV reduction (reuse staging smem) ----
    float* part = (float*)smem;         // 96 rows x 66 floats = 25344B
    if (ns > 0) {
        int pr = (ns - 1) * 32 + 16 * mh + lr;
#pragma unroll
        for (int j = 0; j < 8; j++) {
            *(float2*)(part + pr * 66 + 8 * j + lc)       = make_float2(pv[j][0], pv[j][1]);
            *(float2*)(part + (pr + 8) * 66 + 8 * j + lc) = make_float2(pv[j][2], pv[j][3]);
        }
    }
    __syncthreads();

    if (ns == 0 && ctx_out) {
#pragma unroll
        for (int j = 0; j < 8; j++) {
#pragma unroll
            for (int s = 0; s < 3; s++) {
                int pr = s * 32 + 16 * mh + lr;
                float2 u  = *(float2*)(part + pr * 66 + 8 * j + lc);
                float2 u2 = *(float2*)(part + (pr + 8) * 66 + 8 * j + lc);
                pv[j][0] += u.x;  pv[j][1] += u.y;
                pv[j][2] += u2.x; pv[j][3] += u2.y;
            }
        }
        float i0 = rinv_s[r0], i1 = rinv_s[r0 + 8];
        float* c0 = ctx_out + ((size_t)bh * SS + q0 + r0) * DD;
#pragma unroll
        for (int j = 0; j < 8; j++) {
            *(float2*)(c0 + 8 * j + lc) =
                make_float2(pv[j][0] * i0, pv[j][1] * i0);
            *(float2*)(c0 + 8 * DD + 8 * j + lc) =
                make_float2(pv[j][2] * i1, pv[j][3] * i1);
        }
    }

    // ---- tail: normalize this block's prob rows, NEWEST cols first ----
    if (prob_out) {
        float* pbaseg = prob_out + ((size_t)bh * SS + q0) * SS;
#pragma unroll 4
        for (int it = QT * (SS / 4) / 256 - 1; it >= 0; it--) {
            int i = it * 256 + tid;
            int row = i >> 9;
            int c = (i & 511) * 4;
            float inv = rinv_s[row];
            float4 v = *(float4*)(pbaseg + (size_t)row * SS + c);
            v.x *= inv; v.y *= inv; v.z *= inv; v.w *= inv;
            *(float4*)(pbaseg + (size_t)row * SS + c) = v;
        }
    }
}

extern "C" void kernel_launch(void* const* d_in, const int* in_sizes, int n_in,
                              void* d_out, int out_size)
{
    const float* Q = (const float*)d_in[0];
    const float* K = (const float*)d_in[1];
    const float* V = (const float*)d_in[2];
    const int*   M = (const int*)d_in[3];

    float* ctx = nullptr;
    float* prob = nullptr;
    long long os = out_size;
    if (os >= (long long)(CTX_ELEMS + PROB_ELEMS)) {
        ctx  = (float*)d_out;
        prob = (float*)d_out + CTX_ELEMS;
    } else if (os == (long long)PROB_ELEMS) {
        prob = (float*)d_out;
    } else {
        ctx  = (float*)d_out;
    }

    static bool attr_set = false;
    if (!attr_set) {
        cudaFuncSetAttribute(sdpa_kernel,
                             cudaFuncAttributeMaxDynamicSharedMemorySize, SMEM_BYTES);
        attr_set = true;
    }

    prep_split_kernel<<<(NBH * SS * DD) / 256, 256>>>(K, V);
    sdpa_kernel<<<NBH * (SS / QT), 256, SMEM_BYTES>>>(Q, M, ctx, prob);
}

// round 15
// speedup vs baseline: 1.1738x; 1.1738x over previous
#include <cuda_runtime.h>
#include <cuda_fp16.h>
#include <cstdint>

#define SS 2048
#define DD 64
#define NBH 32
#define QT 32
#define KCH 64
#define NCH 32
#define C_EXP 0.18033688011112042f      // 0.125 * log2(e)

#define CTX_ELEMS (2LL*16*2048*64)
#define PROB_ELEMS (2LL*16*2048*2048)

__device__ __half g_kh[NBH*SS*DD];
__device__ __half g_vh[NBH*SS*DD];

__global__ void prep_split_kernel(const float* __restrict__ K,
                                  const float* __restrict__ V)
{
    int i = blockIdx.x * 256 + threadIdx.x;
    g_kh[i] = __float2half_rn(K[i]);
    g_vh[i] = __float2half_rn(V[i]);
}

// ---------------- smem layout ------------------------------------------------
// K: 2 slots x 9216B   V: 3 slots x 9216B   (64 rows x 144B each)
#define ARR_B    9216
#define OFF_K    0
#define OFF_V    18432
#define OFF_RSUM 46080
#define OFF_RINV 46208
#define SMEM_BYTES 46336

__device__ __forceinline__ uint32_t sptr(const void* p) {
    return (uint32_t)__cvta_generic_to_shared(p);
}
__device__ __forceinline__ void ldmA(uint32_t* a, uint32_t addr) {
    asm volatile("ldmatrix.sync.aligned.m8n8.x4.shared.b16 {%0,%1,%2,%3}, [%4];"
                 : "=r"(a[0]), "=r"(a[1]), "=r"(a[2]), "=r"(a[3]) : "r"(addr));
}
__device__ __forceinline__ void ldmB4(uint32_t* b, uint32_t addr) {
    asm volatile("ldmatrix.sync.aligned.m8n8.x4.shared.b16 {%0,%1,%2,%3}, [%4];"
                 : "=r"(b[0]), "=r"(b[1]), "=r"(b[2]), "=r"(b[3]) : "r"(addr));
}
__device__ __forceinline__ void ldmBT4(uint32_t* b, uint32_t addr) {
    asm volatile("ldmatrix.sync.aligned.m8n8.x4.trans.shared.b16 {%0,%1,%2,%3}, [%4];"
                 : "=r"(b[0]), "=r"(b[1]), "=r"(b[2]), "=r"(b[3]) : "r"(addr));
}
__device__ __forceinline__ void mma16816(float* c, const uint32_t* a, const uint32_t* b) {
    asm volatile("mma.sync.aligned.m16n8k16.row.col.f32.f16.f16.f32 "
                 "{%0,%1,%2,%3}, {%4,%5,%6,%7}, {%8,%9}, {%0,%1,%2,%3};"
                 : "+f"(c[0]), "+f"(c[1]), "+f"(c[2]), "+f"(c[3])
                 : "r"(a[0]), "r"(a[1]), "r"(a[2]), "r"(a[3]), "r"(b[0]), "r"(b[1]));
}
__device__ __forceinline__ void cpa16(uint32_t dst, const void* src) {
    asm volatile("cp.async.cg.shared.global [%0], [%1], 16;" :: "r"(dst), "l"(src));
}
__device__ __forceinline__ void cpa_commit() {
    asm volatile("cp.async.commit_group;");
}
template<int N> __device__ __forceinline__ void cpa_wait() {
    asm volatile("cp.async.wait_group %0;" :: "n"(N));
}
__device__ __forceinline__ float ex2f(float x) {
    float y; asm("ex2.approx.f32 %0, %1;" : "=f"(y) : "f"(x)); return y;
}
__device__ __forceinline__ uint32_t packh2(float a, float b) {
    __half2 t = __floats2half2_rn(a, b);
    return *(uint32_t*)&t;
}

__global__ __launch_bounds__(256, 3)
void sdpa_kernel(const float* __restrict__ Qg_,
                 const int*   __restrict__ Mg_,
                 float* __restrict__ ctx_out,
                 float* __restrict__ prob_out)
{
    extern __shared__ char smem[];
    float* rsum_s = (float*)(smem + OFF_RSUM);
    float* rinv_s = (float*)(smem + OFF_RINV);

    const int tid = threadIdx.x;
    const int w = tid >> 5, l = tid & 31;
    const int bh = blockIdx.x >> 6;
    const int qt = blockIdx.x & 63;
    const int q0 = qt * QT;
    const int b  = bh >> 4;
    const int mh = w & 1;               // m-half: rows 16*mh..
    const int ns = w >> 1;              // key-slice 16*ns.. (0..3)
    const int lr = l >> 2;
    const int lc = (l & 3) * 2;
    const int r0 = 16 * mh + lr;

    const float* Qg = Qg_ + ((size_t)bh * SS + q0) * DD;
    const int*   mg = Mg_ + (size_t)b * SS;

    // ---- Q load via borrowed K-staging smem; rowsum init ----
    __half* qtmp = (__half*)smem;
    for (int i = tid; i < QT * DD; i += 256) {
        int r = i >> 6, d = i & 63;
        qtmp[r * 72 + d] = __float2half_rn(Qg[i]);
    }
    if (tid < 32) rsum_s[tid] = 0.f;
    __syncthreads();

    uint32_t qh[16];
    {
        uint32_t qb = sptr(qtmp) + (16 * mh + (l & 15)) * 144 + (l >> 4) * 16;
#pragma unroll
        for (int kt = 0; kt < 4; kt++) ldmA(qh + 4 * kt, qb + kt * 32);
    }
    __syncthreads();                    // Q consumed; staging free

    // ---- block-cooperative staging (each 16B chunk loaded exactly once) ----
    const __half* gkh = g_kh + (size_t)bh * SS * DD;
    const __half* gvh = g_vh + (size_t)bh * SS * DD;
    const uint32_t sK = sptr(smem) + OFF_K;
    const uint32_t sV = sptr(smem) + OFF_V;

    auto issue = [&](int ch, int kslot, int vslot) {
        const __half* bK = gkh + (size_t)ch * KCH * DD;
        const __half* bV = gvh + (size_t)ch * KCH * DD;
#pragma unroll
        for (int rI = 0; rI < 2; rI++) {
            int rem = rI * 256 + tid;            // 0..511
            int key = rem >> 3, seg = rem & 7;
            uint32_t o = key * 144 + seg * 16;
            int so = key * DD + seg * 8;
            cpa16(sK + kslot * ARR_B + o, bK + so);
            cpa16(sV + vslot * ARR_B + o, bV + so);
        }
        cpa_commit();
    };

    const uint32_t kOff4 = (16 * ns + 8 * (l >> 4) + (l & 7)) * 144
                         + ((l >> 3) & 1) * 16;
    const uint32_t vOff4 = (16 * ns + (l & 15)) * 144 + (l >> 4) * 16;
    float* probRow = prob_out ? prob_out + ((size_t)bh * SS + q0 + r0) * SS : nullptr;

    float pv[8][4] = {};
    float rs0 = 0.f, rs1 = 0.f;
    uint32_t pah[4];                    // P fragments of chunk ch-1

    // QK for one chunk -> acc
    auto QK = [&](int kslot, float acc[2][4]) {
        uint32_t bq[4];
        uint32_t kb_s = sK + kslot * ARR_B + kOff4;
#pragma unroll
        for (int kt = 0; kt < 4; kt++) {
            ldmB4(bq, kb_s + kt * 32);
            mma16816(acc[0], qh + 4 * kt, bq);
            mma16816(acc[1], qh + 4 * kt, bq + 2);
        }
    };
    // epilogue: exp/mask/rowsum/store + pack into pah
    auto EPI = [&](int ch, float acc[2][4]) {
        int kb = ch * KCH + 16 * ns + lc;
#pragma unroll
        for (int t = 0; t < 2; t++) {
            int2 mm = *(const int2*)(mg + kb + 8 * t);
            float p0 = mm.x ? 0.f : ex2f(acc[t][0] * C_EXP);
            float p1 = mm.y ? 0.f : ex2f(acc[t][1] * C_EXP);
            float p2 = mm.x ? 0.f : ex2f(acc[t][2] * C_EXP);
            float p3 = mm.y ? 0.f : ex2f(acc[t][3] * C_EXP);
            rs0 += p0 + p1;
            rs1 += p2 + p3;
            if (probRow) {
                *(float2*)(probRow + kb + 8 * t)          = make_float2(p0, p1);
                *(float2*)(probRow + 8 * SS + kb + 8 * t) = make_float2(p2, p3);
            }
            pah[2 * t]     = packh2(p0, p1);
            pah[2 * t + 1] = packh2(p2, p3);
        }
    };
    // PV for chunk whose P sits in pah
    auto PV = [&](int vslot) {
        uint32_t bv[4];
        uint32_t vb = sV + vslot * ARR_B + vOff4;
#pragma unroll
        for (int jj = 0; jj < 4; jj++) {
            ldmBT4(bv, vb + jj * 32);
            mma16816(pv[2 * jj],     pah, bv);
            mma16816(pv[2 * jj + 1], pah, bv + 2);
        }
    };

    // ---- prologue: chunk 0 ----
    issue(0, 0, 0);
    {
        cpa_wait<0>();
        __syncthreads();
        issue(1, 1, 1);
        float acc[2][4] = {};
        QK(0, acc);
        EPI(0, acc);
    }

    // ---- steady state: QK(ch) + PV(ch-1) overlap ----
    int vprev = 0, vnext = 2;           // (ch-1)%3, (ch+1)%3 for ch=1
#pragma unroll 1
    for (int ch = 1; ch < NCH; ch++) {
        cpa_wait<0>();
        __syncthreads();                // all warps done iter ch-1
        if (ch + 1 < NCH) issue(ch + 1, (ch + 1) & 1, vnext);

        float acc[2][4] = {};
        QK(ch & 1, acc);                // QK(ch)   — indep of pah
        PV(vprev);                      // PV(ch-1) — uses pah, V(ch-1)
        EPI(ch, acc);                   // new pah for next iter

        vprev = (vprev == 2) ? 0 : vprev + 1;
        vnext = (vnext == 2) ? 0 : vnext + 1;
    }
    PV(vprev);                          // PV(31), slot 31%3 == vprev

    // ---- rowsum reduce ----
    rs0 += __shfl_xor_sync(0xffffffffu, rs0, 1);
    rs0 += __shfl_xor_sync(0xffffffffu, rs0, 2);
    rs1 += __shfl_xor_sync(0xffffffffu, rs1, 1);
    rs1 += __shfl_xor_sync(0xffffffffu, rs1, 2);
    if ((l & 3) == 0) {
        atomicAdd(&rsum_s[r0], rs0);
        atomicAdd(&rsum_s[r0 + 8], rs1);
    }
    __syncthreads();                    // staging free, atomics done

    if (tid < 32) rinv_s[tid] = 1.0f / rsum_s[tid];

    // ---- cross-warp PV reduction (reuse staging smem) ----
    float* part = (float*)smem;         // 96 rows x 66 floats = 25344B
    if (ns > 0) {
        int pr = (ns - 1) * 32 + 16 * mh + lr;
#pragma unroll
        for (int j = 0; j < 8; j++) {
            *(float2*)(part + pr * 66 + 8 * j + lc)       = make_float2(pv[j][0], pv[j][1]);
            *(float2*)(part + (pr + 8) * 66 + 8 * j + lc) = make_float2(pv[j][2], pv[j][3]);
        }
    }
    __syncthreads();

    if (ns == 0 && ctx_out) {
#pragma unroll
        for (int j = 0; j < 8; j++) {
#pragma unroll
            for (int s = 0; s < 3; s++) {
                int pr = s * 32 + 16 * mh + lr;
                float2 u  = *(float2*)(part + pr * 66 + 8 * j + lc);
                float2 u2 = *(float2*)(part + (pr + 8) * 66 + 8 * j + lc);
                pv[j][0] += u.x;  pv[j][1] += u.y;
                pv[j][2] += u2.x; pv[j][3] += u2.y;
            }
        }
        float i0 = rinv_s[r0], i1 = rinv_s[r0 + 8];
        float* c0 = ctx_out + ((size_t)bh * SS + q0 + r0) * DD;
#pragma unroll
        for (int j = 0; j < 8; j++) {
            *(float2*)(c0 + 8 * j + lc) =
                make_float2(pv[j][0] * i0, pv[j][1] * i0);
            *(float2*)(c0 + 8 * DD + 8 * j + lc) =
                make_float2(pv[j][2] * i1, pv[j][3] * i1);
        }
    }

    // ---- tail: normalize this block's prob rows ----
    if (prob_out) {
        float* pbaseg = prob_out + ((size_t)bh * SS + q0) * SS;
#pragma unroll 4
        for (int i = tid; i < QT * (SS / 4); i += 256) {
            int row = i >> 9;
            int c = (i & 511) * 4;
            float inv = rinv_s[row];
            float4 v = *(float4*)(pbaseg + (size_t)row * SS + c);
            v.x *= inv; v.y *= inv; v.z *= inv; v.w *= inv;
            *(float4*)(pbaseg + (size_t)row * SS + c) = v;
        }
    }
}

extern "C" void kernel_launch(void* const* d_in, const int* in_sizes, int n_in,
                              void* d_out, int out_size)
{
    const float* Q = (const float*)d_in[0];
    const float* K = (const float*)d_in[1];
    const float* V = (const float*)d_in[2];
    const int*   M = (const int*)d_in[3];

    float* ctx = nullptr;
    float* prob = nullptr;
    long long os = out_size;
    if (os >= (long long)(CTX_ELEMS + PROB_ELEMS)) {
        ctx  = (float*)d_out;
        prob = (float*)d_out + CTX_ELEMS;
    } else if (os == (long long)PROB_ELEMS) {
        prob = (float*)d_out;
    } else {
        ctx  = (float*)d_out;
    }

    static bool attr_set = false;
    if (!attr_set) {
        cudaFuncSetAttribute(sdpa_kernel,
                             cudaFuncAttributeMaxDynamicSharedMemorySize, SMEM_BYTES);
        attr_set = true;
    }

    prep_split_kernel<<<(NBH * SS * DD) / 256, 256>>>(K, V);
    sdpa_kernel<<<NBH * (SS / QT), 256, SMEM_BYTES>>>(Q, M, ctx, prob);
}

// round 17
// speedup vs baseline: 1.5635x; 1.3320x over previous
#include <cuda_runtime.h>
#include <cuda_fp16.h>
#include <cstdint>

#define SS 2048
#define DD 64
#define NBH 32
#define QT 32
#define KCH 64
#define NCH 32
#define C_EXP 0.18033688011112042f      // 0.125 * log2(e)

#define CTX_ELEMS (2LL*16*2048*64)
#define PROB_ELEMS (2LL*16*2048*2048)

__device__ __half g_kh[NBH*SS*DD];
__device__ __half g_vh[NBH*SS*DD];

__global__ void prep_split_kernel(const float* __restrict__ K,
                                  const float* __restrict__ V)
{
    int i = blockIdx.x * 256 + threadIdx.x;
    g_kh[i] = __float2half_rn(K[i]);
    g_vh[i] = __float2half_rn(V[i]);
}

// ---------------- smem layout ------------------------------------------------
// K: 2 slots x 9216B | V: 2 slots x 9216B  (64 rows x 144B each)
#define ARR_B    9216
#define OFF_K    0
#define OFF_V    18432
#define OFF_RSUM 36864
#define OFF_LGS  36992
#define SMEM_BYTES 37120

__device__ __forceinline__ uint32_t sptr(const void* p) {
    return (uint32_t)__cvta_generic_to_shared(p);
}
__device__ __forceinline__ void ldmA(uint32_t* a, uint32_t addr) {
    asm volatile("ldmatrix.sync.aligned.m8n8.x4.shared.b16 {%0,%1,%2,%3}, [%4];"
                 : "=r"(a[0]), "=r"(a[1]), "=r"(a[2]), "=r"(a[3]) : "r"(addr));
}
__device__ __forceinline__ void ldmB4(uint32_t* b, uint32_t addr) {
    asm volatile("ldmatrix.sync.aligned.m8n8.x4.shared.b16 {%0,%1,%2,%3}, [%4];"
                 : "=r"(b[0]), "=r"(b[1]), "=r"(b[2]), "=r"(b[3]) : "r"(addr));
}
__device__ __forceinline__ void ldmBT4(uint32_t* b, uint32_t addr) {
    asm volatile("ldmatrix.sync.aligned.m8n8.x4.trans.shared.b16 {%0,%1,%2,%3}, [%4];"
                 : "=r"(b[0]), "=r"(b[1]), "=r"(b[2]), "=r"(b[3]) : "r"(addr));
}
__device__ __forceinline__ void mma16816(float* c, const uint32_t* a, const uint32_t* b) {
    asm volatile("mma.sync.aligned.m16n8k16.row.col.f32.f16.f16.f32 "
                 "{%0,%1,%2,%3}, {%4,%5,%6,%7}, {%8,%9}, {%0,%1,%2,%3};"
                 : "+f"(c[0]), "+f"(c[1]), "+f"(c[2]), "+f"(c[3])
                 : "r"(a[0]), "r"(a[1]), "r"(a[2]), "r"(a[3]), "r"(b[0]), "r"(b[1]));
}
__device__ __forceinline__ void cpa16(uint32_t dst, const void* src) {
    asm volatile("cp.async.cg.shared.global [%0], [%1], 16;" :: "r"(dst), "l"(src));
}
__device__ __forceinline__ void cpa_commit() {
    asm volatile("cp.async.commit_group;");
}
template<int N> __device__ __forceinline__ void cpa_wait() {
    asm volatile("cp.async.wait_group %0;" :: "n"(N));
}
__device__ __forceinline__ float ex2f(float x) {
    float y; asm("ex2.approx.f32 %0, %1;" : "=f"(y) : "f"(x)); return y;
}
__device__ __forceinline__ uint32_t packh2(float a, float b) {
    __half2 t = __floats2half2_rn(a, b);
    return *(uint32_t*)&t;
}
__device__ __forceinline__ void stcs2(float* p, float a, float b) {
    asm volatile("st.global.cs.v2.f32 [%0], {%1,%2};" :: "l"(p), "f"(a), "f"(b));
}

__global__ __launch_bounds__(256, 3)
void sdpa_kernel(const float* __restrict__ Qg_,
                 const int*   __restrict__ Mg_,
                 float* __restrict__ ctx_out,
                 float* __restrict__ prob_out)
{
    extern __shared__ char smem[];
    float* rsum_s = (float*)(smem + OFF_RSUM);
    float* lgs_s  = (float*)(smem + OFF_LGS);

    const int tid = threadIdx.x;
    const int w = tid >> 5, l = tid & 31;
    const int bh = blockIdx.x >> 6;
    const int qt = blockIdx.x & 63;
    const int q0 = qt * QT;
    const int b  = bh >> 4;
    const int mh = w & 1;               // m-half: rows 16*mh..
    const int ns = w >> 1;              // key-slice 16*ns.. (0..3)
    const int lr = l >> 2;
    const int lc = (l & 3) * 2;
    const int r0 = 16 * mh + lr;

    const float* Qg = Qg_ + ((size_t)bh * SS + q0) * DD;
    const int*   mg = Mg_ + (size_t)b * SS;

    // ---- Q load via borrowed staging smem; rowsum init ----
    __half* qtmp = (__half*)smem;
    for (int i = tid; i < QT * DD; i += 256) {
        int r = i >> 6, d = i & 63;
        qtmp[r * 72 + d] = __float2half_rn(Qg[i]);
    }
    if (tid < 32) rsum_s[tid] = 0.f;
    __syncthreads();

    uint32_t qh[16];
    {
        uint32_t qb = sptr(qtmp) + (16 * mh + (l & 15)) * 144 + (l >> 4) * 16;
#pragma unroll
        for (int kt = 0; kt < 4; kt++) ldmA(qh + 4 * kt, qb + kt * 32);
    }
    __syncthreads();                    // Q consumed; staging free

    const __half* gkh = g_kh + (size_t)bh * SS * DD;
    const __half* gvh = g_vh + (size_t)bh * SS * DD;
    const uint32_t sK = sptr(smem) + OFF_K;
    const uint32_t sV = sptr(smem) + OFF_V;

    // coalesced staging: thread tid -> (key, seg); 512 x 16B per array
    auto issueK = [&](int ch) {
        const __half* bK = gkh + (size_t)ch * KCH * DD;
        uint32_t slot = sK + (ch & 1) * ARR_B;
#pragma unroll
        for (int rI = 0; rI < 2; rI++) {
            int rem = rI * 256 + tid;
            int key = rem >> 3, seg = rem & 7;
            cpa16(slot + key * 144 + seg * 16, bK + key * DD + seg * 8);
        }
        cpa_commit();
    };
    auto issueKV = [&](int ch) {
        const __half* bK = gkh + (size_t)ch * KCH * DD;
        const __half* bV = gvh + (size_t)ch * KCH * DD;
        uint32_t ks = sK + (ch & 1) * ARR_B;
        uint32_t vs = sV + (ch & 1) * ARR_B;
#pragma unroll
        for (int rI = 0; rI < 2; rI++) {
            int rem = rI * 256 + tid;
            int key = rem >> 3, seg = rem & 7;
            uint32_t o = key * 144 + seg * 16;
            int so = key * DD + seg * 8;
            cpa16(ks + o, bK + so);
            cpa16(vs + o, bV + so);
        }
        cpa_commit();
    };

    const uint32_t kOff4 = (16 * ns + 8 * (l >> 4) + (l & 7)) * 144
                         + ((l >> 3) & 1) * 16;
    const uint32_t vOff4 = (16 * ns + (l & 15)) * 144 + (l >> 4) * 16;

    auto QK = [&](int ch, float acc[2][4]) {
        uint32_t bq[4];
        uint32_t kb_s = sK + (ch & 1) * ARR_B + kOff4;
#pragma unroll
        for (int kt = 0; kt < 4; kt++) {
            ldmB4(bq, kb_s + kt * 32);
            mma16816(acc[0], qh + 4 * kt, bq);
            mma16816(acc[1], qh + 4 * kt, bq + 2);
        }
    };

    // =================== PASS A: rowsums only ===============================
    float rs0 = 0.f, rs1 = 0.f;
    issueK(0);
#pragma unroll 1
    for (int ch = 0; ch < NCH; ch++) {
        cpa_wait<0>();
        __syncthreads();
        if (ch + 1 < NCH) issueK(ch + 1);

        float acc[2][4] = {};
        QK(ch, acc);

        int kb = ch * KCH + 16 * ns + lc;
#pragma unroll
        for (int t = 0; t < 2; t++) {
            int2 mm = *(const int2*)(mg + kb + 8 * t);
            rs0 += (mm.x ? 0.f : ex2f(acc[t][0] * C_EXP))
                 + (mm.y ? 0.f : ex2f(acc[t][1] * C_EXP));
            rs1 += (mm.x ? 0.f : ex2f(acc[t][2] * C_EXP))
                 + (mm.y ? 0.f : ex2f(acc[t][3] * C_EXP));
        }
    }

    // ---- rowsum reduce -> lg = -log2(rsum) ----
    rs0 += __shfl_xor_sync(0xffffffffu, rs0, 1);
    rs0 += __shfl_xor_sync(0xffffffffu, rs0, 2);
    rs1 += __shfl_xor_sync(0xffffffffu, rs1, 1);
    rs1 += __shfl_xor_sync(0xffffffffu, rs1, 2);
    if ((l & 3) == 0) {
        atomicAdd(&rsum_s[r0], rs0);
        atomicAdd(&rsum_s[r0 + 8], rs1);
    }
    __syncthreads();
    if (tid < 32) lgs_s[tid] = -__log2f(rsum_s[tid]);
    __syncthreads();
    const float lg0 = lgs_s[r0], lg1 = lgs_s[r0 + 8];

    // =================== PASS B: normalized probs + PV ======================
    float pv[8][4] = {};
    float* probRow = prob_out ? prob_out + ((size_t)bh * SS + q0 + r0) * SS : nullptr;

    issueKV(0);
#pragma unroll 1
    for (int ch = 0; ch < NCH; ch++) {
        cpa_wait<0>();
        __syncthreads();
        if (ch + 1 < NCH) issueKV(ch + 1);

        float acc[2][4] = {};
        QK(ch, acc);

        int kb = ch * KCH + 16 * ns + lc;
        uint32_t pah[4];
#pragma unroll
        for (int t = 0; t < 2; t++) {
            int2 mm = *(const int2*)(mg + kb + 8 * t);
            float p0 = mm.x ? 0.f : ex2f(acc[t][0] * C_EXP + lg0);
            float p1 = mm.y ? 0.f : ex2f(acc[t][1] * C_EXP + lg0);
            float p2 = mm.x ? 0.f : ex2f(acc[t][2] * C_EXP + lg1);
            float p3 = mm.y ? 0.f : ex2f(acc[t][3] * C_EXP + lg1);
            pah[2 * t]     = packh2(p0, p1);
            pah[2 * t + 1] = packh2(p2, p3);
            if (probRow) {
                stcs2(probRow + kb + 8 * t, p0, p1);
                stcs2(probRow + 8 * SS + kb + 8 * t, p2, p3);
            }
        }

        // PV (P already normalized)
        uint32_t bv[4];
        uint32_t vb = sV + (ch & 1) * ARR_B + vOff4;
#pragma unroll
        for (int jj = 0; jj < 4; jj++) {
            ldmBT4(bv, vb + jj * 32);
            mma16816(pv[2 * jj],     pah, bv);
            mma16816(pv[2 * jj + 1], pah, bv + 2);
        }
    }

    // ---- cross-warp PV reduction (reuse staging smem) ----
    __syncthreads();                    // all staging reads done
    float* part = (float*)smem;         // 96 rows x 66 floats = 25344B
    if (ns > 0) {
        int pr = (ns - 1) * 32 + 16 * mh + lr;
#pragma unroll
        for (int j = 0; j < 8; j++) {
            *(float2*)(part + pr * 66 + 8 * j + lc)       = make_float2(pv[j][0], pv[j][1]);
            *(float2*)(part + (pr + 8) * 66 + 8 * j + lc) = make_float2(pv[j][2], pv[j][3]);
        }
    }
    __syncthreads();

    if (ns == 0 && ctx_out) {
#pragma unroll
        for (int j = 0; j < 8; j++) {
#pragma unroll
            for (int s = 0; s < 3; s++) {
                int pr = s * 32 + 16 * mh + lr;
                float2 u  = *(float2*)(part + pr * 66 + 8 * j + lc);
                float2 u2 = *(float2*)(part + (pr + 8) * 66 + 8 * j + lc);
                pv[j][0] += u.x;  pv[j][1] += u.y;
                pv[j][2] += u2.x; pv[j][3] += u2.y;
            }
        }
        float* c0 = ctx_out + ((size_t)bh * SS + q0 + r0) * DD;
#pragma unroll
        for (int j = 0; j < 8; j++) {
            *(float2*)(c0 + 8 * j + lc)          = make_float2(pv[j][0], pv[j][1]);
            *(float2*)(c0 + 8 * DD + 8 * j + lc) = make_float2(pv[j][2], pv[j][3]);
        }
    }
}

extern "C" void kernel_launch(void* const* d_in, const int* in_sizes, int n_in,
                              void* d_out, int out_size)
{
    const float* Q = (const float*)d_in[0];
    const float* K = (const float*)d_in[1];
    const float* V = (const float*)d_in[2];
    const int*   M = (const int*)d_in[3];

    float* ctx = nullptr;
    float* prob = nullptr;
    long long os = out_size;
    if (os >= (long long)(CTX_ELEMS + PROB_ELEMS)) {
        ctx  = (float*)d_out;
        prob = (float*)d_out + CTX_ELEMS;
    } else if (os == (long long)PROB_ELEMS) {
        prob = (float*)d_out;
    } else {
        ctx  = (float*)d_out;
    }

    static bool attr_set = false;
    if (!attr_set) {
        cudaFuncSetAttribute(sdpa_kernel,
                             cudaFuncAttributeMaxDynamicSharedMemorySize, SMEM_BYTES);
        attr_set = true;
    }

    prep_split_kernel<<<(NBH * SS * DD) / 256, 256>>>(K, V);
    sdpa_kernel<<<NBH * (SS / QT), 256, SMEM_BYTES>>>(Q, M, ctx, prob);
}